// round 2
// baseline (speedup 1.0000x reference)
#include <cuda_runtime.h>

#define L2E 1.4426950408889634f

static constexpr int Bc = 2, Cc = 8, Hc = 1088, Wc = 1920;
static constexpr int TW = 64, TH = 16, HALO = 4;       // dilation=2, radius=2 -> halo 4
static constexpr int RW = TW + 2 * HALO;               // 72
static constexpr int RH = TH + 2 * HALO;               // 24
static constexpr int SMEM_BYTES = RH * RW * (16 + 16 + 4);  // A(float4)+B(float4)+S(float) = 62208

// Precomputed coefficients (written by setup kernel, read by main kernel)
__device__ float g_rcp[8];   // -p[c]^2 * log2(e)
__device__ float g_lw[25];   // log2(tk[t]) + log2(e)*(sx*dx^2 + sy*dy^2)

__global__ void bf_setup(const float* __restrict__ params,
                         const float* __restrict__ kern) {
    if (threadIdx.x == 0) {
        float p[10];
#pragma unroll
        for (int i = 0; i < 10; i++) p[i] = params[i];
#pragma unroll
        for (int c = 0; c < 8; c++) g_rcp[c] = -p[c] * p[c] * L2E;
        float sx = -p[8] * p[8];
        float sy = -p[9] * p[9];
        // softmax(kernel.flatten() / K), K = 5
        float k[25], m = -1e30f;
        for (int i = 0; i < 25; i++) { k[i] = kern[i] * 0.2f; m = fmaxf(m, k[i]); }
        float s = 0.f;
        for (int i = 0; i < 25; i++) { k[i] = expf(k[i] - m); s += k[i]; }
        float inv = 1.0f / s;
        for (int t = 0; t < 25; t++) {
            int ky = t / 5, kx = t % 5;
            float dy = (float)((ky - 2) * 2);   // dilation = 2
            float dx = (float)((kx - 2) * 2);
            g_lw[t] = log2f(k[t] * inv) + L2E * (sx * dx * dx + sy * dy * dy);
        }
    }
}

template <int DYN>
__global__ __launch_bounds__(256)
void bf_main(const float* __restrict__ inp, float* __restrict__ out) {
    extern __shared__ float smem[];
    float4* sA = (float4*)smem;           // channels 0..3
    float4* sB = sA + RH * RW;            // channels 4..7
    float*  sS = (float*)(sB + RH * RW);  // s = sum_c rc_c * v_c^2  (or -1e30 if OOB)

    const int b  = blockIdx.z;
    const int x0 = blockIdx.x * TW - HALO;
    const int y0 = blockIdx.y * TH - HALO;

    float rc[8];
#pragma unroll
    for (int c = 0; c < 8; c++) rc[c] = g_rcp[c];

    const float* ibase = inp + (size_t)b * Cc * Hc * Wc;

    // ---- cooperative tile load: global (planar) -> smem (pixel-major float4 pairs) ----
    for (int i = threadIdx.x; i < RH * RW; i += 256) {
        int ry = i / RW, rx = i - ry * RW;
        int gy = y0 + ry, gx = x0 + rx;
        float v[8];
        float s;
        if ((unsigned)gy < (unsigned)Hc && (unsigned)gx < (unsigned)Wc) {
            const float* p = ibase + gy * Wc + gx;
#pragma unroll
            for (int c = 0; c < 8; c++) v[c] = p[c * Hc * Wc];
            s = 0.f;
#pragma unroll
            for (int c = 0; c < 8; c++) s = fmaf(rc[c] * v[c], v[c], s);
        } else {
#pragma unroll
            for (int c = 0; c < 8; c++) v[c] = 0.f;
            s = -1e30f;   // sentinel: ex2(arg) -> 0, so this tap contributes nothing
        }
        sA[i] = make_float4(v[0], v[1], v[2], v[3]);
        sB[i] = make_float4(v[4], v[5], v[6], v[7]);
        sS[i] = s;
    }

    float lw[25];
#pragma unroll
    for (int t = 0; t < 25; t++) lw[t] = g_lw[t];

    __syncthreads();

    const int tx = threadIdx.x & 63;
    const int tr = threadIdx.x >> 6;

#pragma unroll
    for (int j = 0; j < 4; j++) {
        const int row = tr + j * 4;                    // 0..15
        const int ci  = (HALO + row) * RW + HALO + tx; // center index in region
        const float4 ca = sA[ci];
        const float4 cb = sB[ci];
        const float  sc = sS[ci];
        const float q0 = rc[0] * ca.x, q1 = rc[1] * ca.y, q2 = rc[2] * ca.z, q3 = rc[3] * ca.w;
        const float q4 = rc[4] * cb.x, q5 = rc[5] * cb.y, q6 = rc[6] * cb.z, q7 = rc[7] * cb.w;

        float num[DYN];
#pragma unroll
        for (int c = 0; c < DYN; c++) num[c] = 0.f;
        float den = 0.f;

#pragma unroll
        for (int ky = 0; ky < 5; ky++) {
#pragma unroll
            for (int kx = 0; kx < 5; kx++) {
                const int ni = ci + ((ky - 2) * 2) * RW + (kx - 2) * 2;
                const float4 na = sA[ni];
                const float4 nb = sB[ni];
                const float  sn = sS[ni];
                // d2' = sc + sn - 2 * sum_c q_c * n_c   (all pre-scaled by log2 e)
                float dA = fmaf(q3, na.w, fmaf(q2, na.z, fmaf(q1, na.y, q0 * na.x)));
                float dB = fmaf(q7, nb.w, fmaf(q6, nb.z, fmaf(q5, nb.y, q4 * nb.x)));
                float arg = fmaf(dA + dB, -2.0f, sn + (sc + lw[ky * 5 + kx]));
                float w;
                asm("ex2.approx.ftz.f32 %0, %1;" : "=f"(w) : "f"(arg));
                den += w;
                const float nv[8] = {na.x, na.y, na.z, na.w, nb.x, nb.y, nb.z, nb.w};
#pragma unroll
                for (int c = 0; c < DYN; c++) num[c] = fmaf(w, nv[c], num[c]);
            }
        }

        float rden;
        asm("rcp.approx.ftz.f32 %0, %1;" : "=f"(rden) : "f"(den));

        const int gy = blockIdx.y * TH + row;
        const int gx = blockIdx.x * TW + tx;
        if (gy < Hc && gx < Wc) {
            float* op = out + (((size_t)b * DYN) * Hc + gy) * Wc + gx;
#pragma unroll
            for (int c = 0; c < DYN; c++) op[(size_t)c * Hc * Wc] = num[c] * rden;
        }
    }
}

extern "C" void kernel_launch(void* const* d_in, const int* in_sizes, int n_in,
                              void* d_out, int out_size) {
    const float* inp    = (const float*)d_in[0];
    const float* params = (const float*)d_in[1];
    const float* kern   = (const float*)d_in[2];
    float* out = (float*)d_out;
    (void)in_sizes; (void)n_in;

    int dyn = out_size / (Bc * Hc * Wc);   // dynamic_size derived from output element count
    if (dyn < 1) dyn = 1;
    if (dyn > 8) dyn = 8;

    bf_setup<<<1, 32>>>(params, kern);

    dim3 grid(Wc / TW, (Hc + TH - 1) / TH, Bc);

#define BF_LAUNCH(D)                                                                     \
    {                                                                                    \
        cudaFuncSetAttribute(bf_main<D>, cudaFuncAttributeMaxDynamicSharedMemorySize,    \
                             SMEM_BYTES);                                                \
        bf_main<D><<<grid, 256, SMEM_BYTES>>>(inp, out);                                 \
    }

    switch (dyn) {
        case 1: BF_LAUNCH(1); break;
        case 2: BF_LAUNCH(2); break;
        case 3: BF_LAUNCH(3); break;
        case 4: BF_LAUNCH(4); break;
        case 5: BF_LAUNCH(5); break;
        case 6: BF_LAUNCH(6); break;
        case 7: BF_LAUNCH(7); break;
        case 8: BF_LAUNCH(8); break;
        default: BF_LAUNCH(3); break;
    }
#undef BF_LAUNCH
}

// round 6
// speedup vs baseline: 1.4309x; 1.4309x over previous
#include <cuda_runtime.h>

#define L2E 1.4426950408889634f

static constexpr int Bc = 2, Cc = 8, Hc = 1088, Wc = 1920;
static constexpr int TW = 64, TH = 16, HALO = 4;       // dilation=2, radius=2 -> halo 4
static constexpr int RW = TW + 2 * HALO;               // 72
static constexpr int RH = TH + 2 * HALO;               // 24
// A(float4) + B(float4) + S(float) per region pixel, + 32 floats of coeffs
static constexpr int SMEM_BYTES = RH * RW * (16 + 16 + 4) + 32 * 4;

// Precomputed coefficients (written by setup kernel, read by main kernel)
__device__ float g_rcp[8];   // -p[c]^2 * log2(e)
__device__ float g_lw[25];   // log2(tk[t]) + log2(e)*(sx*dx^2 + sy*dy^2)

__global__ void bf_setup(const float* __restrict__ params,
                         const float* __restrict__ kern) {
    if (threadIdx.x == 0) {
        float p[10];
#pragma unroll
        for (int i = 0; i < 10; i++) p[i] = params[i];
#pragma unroll
        for (int c = 0; c < 8; c++) g_rcp[c] = -p[c] * p[c] * L2E;
        float sx = -p[8] * p[8];
        float sy = -p[9] * p[9];
        // softmax(kernel.flatten() / K), K = 5
        float k[25], m = -1e30f;
        for (int i = 0; i < 25; i++) { k[i] = kern[i] * 0.2f; m = fmaxf(m, k[i]); }
        float s = 0.f;
        for (int i = 0; i < 25; i++) { k[i] = expf(k[i] - m); s += k[i]; }
        float inv = 1.0f / s;
        for (int t = 0; t < 25; t++) {
            int ky = t / 5, kx = t % 5;
            float dy = (float)((ky - 2) * 2);   // dilation = 2
            float dx = (float)((kx - 2) * 2);
            g_lw[t] = log2f(k[t] * inv) + L2E * (sx * dx * dx + sy * dy * dy);
        }
    }
}

template <int DYN>
__global__ __launch_bounds__(256, 2)
void bf_main(const float* __restrict__ inp, float* __restrict__ out) {
    extern __shared__ float smem[];
    float4* sA = (float4*)smem;           // channels 0..3
    float4* sB = sA + RH * RW;            // channels 4..7
    float*  sS = (float*)(sB + RH * RW);  // s = sum_c rc_c * v_c^2  (or -1e30 if OOB)
    float*  sLW = sS + RH * RW;           // 25 tap constants (broadcast reads)

    const int b  = blockIdx.z;
    const int x0 = blockIdx.x * TW - HALO;
    const int y0 = blockIdx.y * TH - HALO;

    // stage tap coefficients into smem (broadcast LDS, conflict-free)
    if (threadIdx.x < 25) sLW[threadIdx.x] = g_lw[threadIdx.x];

    float rc[8];
#pragma unroll
    for (int c = 0; c < 8; c++) rc[c] = g_rcp[c];

    const float* ibase = inp + (size_t)b * Cc * Hc * Wc;

    // ---- cooperative tile load: global (planar) -> smem (pixel-major float4 pairs) ----
    for (int i = threadIdx.x; i < RH * RW; i += 256) {
        int ry = i / RW, rx = i - ry * RW;
        int gy = y0 + ry, gx = x0 + rx;
        float v[8];
        float s;
        if ((unsigned)gy < (unsigned)Hc && (unsigned)gx < (unsigned)Wc) {
            const float* p = ibase + gy * Wc + gx;
#pragma unroll
            for (int c = 0; c < 8; c++) v[c] = p[c * Hc * Wc];
            s = 0.f;
#pragma unroll
            for (int c = 0; c < 8; c++) s = fmaf(rc[c] * v[c], v[c], s);
        } else {
#pragma unroll
            for (int c = 0; c < 8; c++) v[c] = 0.f;
            s = -1e30f;   // sentinel: ex2(arg) -> 0, so this tap contributes nothing
        }
        sA[i] = make_float4(v[0], v[1], v[2], v[3]);
        sB[i] = make_float4(v[4], v[5], v[6], v[7]);
        sS[i] = s;
    }

    __syncthreads();

    const int tx = threadIdx.x & 63;
    const int tr = threadIdx.x >> 6;

#pragma unroll 1
    for (int j = 0; j < 4; j++) {
        const int row = tr + j * 4;                    // 0..15
        const int ci  = (HALO + row) * RW + HALO + tx; // center index in region
        const float4 ca = sA[ci];
        const float4 cb = sB[ci];
        const float  sc = sS[ci];
        const float q0 = rc[0] * ca.x, q1 = rc[1] * ca.y, q2 = rc[2] * ca.z, q3 = rc[3] * ca.w;
        const float q4 = rc[4] * cb.x, q5 = rc[5] * cb.y, q6 = rc[6] * cb.z, q7 = rc[7] * cb.w;

        float num[DYN];
#pragma unroll
        for (int c = 0; c < DYN; c++) num[c] = 0.f;
        float den = 0.f;

#pragma unroll
        for (int ky = 0; ky < 5; ky++) {
#pragma unroll
            for (int kx = 0; kx < 5; kx++) {
                const int ni = ci + ((ky - 2) * 2) * RW + (kx - 2) * 2;
                const float4 na = sA[ni];
                const float4 nb = sB[ni];
                const float  sn = sS[ni];
                // d2' = sc + sn - 2 * sum_c q_c * n_c   (all pre-scaled by log2 e)
                float dA = fmaf(q3, na.w, fmaf(q2, na.z, fmaf(q1, na.y, q0 * na.x)));
                float dB = fmaf(q7, nb.w, fmaf(q6, nb.z, fmaf(q5, nb.y, q4 * nb.x)));
                float arg = fmaf(dA + dB, -2.0f, sn + (sc + sLW[ky * 5 + kx]));
                float w;
                asm("ex2.approx.ftz.f32 %0, %1;" : "=f"(w) : "f"(arg));
                den += w;
                const float nv[8] = {na.x, na.y, na.z, na.w, nb.x, nb.y, nb.z, nb.w};
#pragma unroll
                for (int c = 0; c < DYN; c++) num[c] = fmaf(w, nv[c], num[c]);
            }
        }

        float rden;
        asm("rcp.approx.ftz.f32 %0, %1;" : "=f"(rden) : "f"(den));

        // exact grid: 1088 = 68*16, 1920 = 30*64 -> no bounds check needed
        const int gy = blockIdx.y * TH + row;
        const int gx = blockIdx.x * TW + tx;
        float* op = out + (((size_t)b * DYN) * Hc + gy) * Wc + gx;
#pragma unroll
        for (int c = 0; c < DYN; c++) op[(size_t)c * Hc * Wc] = num[c] * rden;
    }
}

extern "C" void kernel_launch(void* const* d_in, const int* in_sizes, int n_in,
                              void* d_out, int out_size) {
    const float* inp    = (const float*)d_in[0];
    const float* params = (const float*)d_in[1];
    const float* kern   = (const float*)d_in[2];
    float* out = (float*)d_out;
    (void)in_sizes; (void)n_in;

    int dyn = out_size / (Bc * Hc * Wc);   // dynamic_size derived from output element count
    if (dyn < 1) dyn = 1;
    if (dyn > 8) dyn = 8;

    bf_setup<<<1, 32>>>(params, kern);

    dim3 grid(Wc / TW, (Hc + TH - 1) / TH, Bc);

#define BF_LAUNCH(D)                                                                     \
    {                                                                                    \
        cudaFuncSetAttribute(bf_main<D>, cudaFuncAttributeMaxDynamicSharedMemorySize,    \
                             SMEM_BYTES);                                                \
        bf_main<D><<<grid, 256, SMEM_BYTES>>>(inp, out);                                 \
    }

    switch (dyn) {
        case 1: BF_LAUNCH(1); break;
        case 2: BF_LAUNCH(2); break;
        case 3: BF_LAUNCH(3); break;
        case 4: BF_LAUNCH(4); break;
        case 5: BF_LAUNCH(5); break;
        case 6: BF_LAUNCH(6); break;
        case 7: BF_LAUNCH(7); break;
        case 8: BF_LAUNCH(8); break;
        default: BF_LAUNCH(3); break;
    }
#undef BF_LAUNCH
}

// round 8
// speedup vs baseline: 1.5743x; 1.1002x over previous
#include <cuda_runtime.h>

#define L2E 1.4426950408889634f

static constexpr int Bc = 2, Cc = 8, Hc = 1088, Wc = 1920;
static constexpr int TW = 64, TH = 16, HALO = 4;       // dilation=2, radius=2 -> halo 4
static constexpr int RW = TW + 2 * HALO;               // 72
static constexpr int RH = TH + 2 * HALO;               // 24
// A(float4) + B(float4) + S(float) per region pixel, + 32 floats of coeffs
static constexpr int SMEM_BYTES = RH * RW * (16 + 16 + 4) + 32 * 4;

// Precomputed coefficients (written by setup kernel, read by main kernel)
__device__ float g_rcp[8];   // -p[c]^2 * log2(e)
__device__ float g_lw[25];   // log2(tk[t]) + log2(e)*(sx*dx^2 + sy*dy^2)

__global__ void bf_setup(const float* __restrict__ params,
                         const float* __restrict__ kern) {
    if (threadIdx.x == 0) {
        float p[10];
#pragma unroll
        for (int i = 0; i < 10; i++) p[i] = params[i];
#pragma unroll
        for (int c = 0; c < 8; c++) g_rcp[c] = -p[c] * p[c] * L2E;
        float sx = -p[8] * p[8];
        float sy = -p[9] * p[9];
        // softmax(kernel.flatten() / K), K = 5
        float k[25], m = -1e30f;
        for (int i = 0; i < 25; i++) { k[i] = kern[i] * 0.2f; m = fmaxf(m, k[i]); }
        float s = 0.f;
        for (int i = 0; i < 25; i++) { k[i] = expf(k[i] - m); s += k[i]; }
        float inv = 1.0f / s;
        for (int t = 0; t < 25; t++) {
            int ky = t / 5, kx = t % 5;
            float dy = (float)((ky - 2) * 2);   // dilation = 2
            float dx = (float)((kx - 2) * 2);
            g_lw[t] = log2f(k[t] * inv) + L2E * (sx * dx * dx + sy * dy * dy);
        }
    }
}

template <int DYN>
__global__ __launch_bounds__(256, 2)
void bf_main(const float* __restrict__ inp, float* __restrict__ out) {
    extern __shared__ float smem[];
    float4* sA = (float4*)smem;           // channels 0..3
    float4* sB = sA + RH * RW;            // channels 4..7
    float*  sS = (float*)(sB + RH * RW);  // s = sum_c rc_c * v_c^2  (or -1e30 if OOB)
    float*  sLW = sS + RH * RW;           // 25 tap constants (broadcast reads)

    const int b  = blockIdx.z;
    const int x0 = blockIdx.x * TW - HALO;
    const int y0 = blockIdx.y * TH - HALO;

    // stage tap coefficients into smem (broadcast LDS, conflict-free)
    if (threadIdx.x < 25) sLW[threadIdx.x] = g_lw[threadIdx.x];

    float rc[8];
#pragma unroll
    for (int c = 0; c < 8; c++) rc[c] = g_rcp[c];

    const float* ibase = inp + (size_t)b * Cc * Hc * Wc;

    // ---- cooperative tile load: global (planar) -> smem (pixel-major float4 pairs) ----
    for (int i = threadIdx.x; i < RH * RW; i += 256) {
        int ry = i / RW, rx = i - ry * RW;
        int gy = y0 + ry, gx = x0 + rx;
        float v[8];
        float s;
        if ((unsigned)gy < (unsigned)Hc && (unsigned)gx < (unsigned)Wc) {
            const float* p = ibase + gy * Wc + gx;
#pragma unroll
            for (int c = 0; c < 8; c++) v[c] = p[c * Hc * Wc];
            s = 0.f;
#pragma unroll
            for (int c = 0; c < 8; c++) s = fmaf(rc[c] * v[c], v[c], s);
        } else {
#pragma unroll
            for (int c = 0; c < 8; c++) v[c] = 0.f;
            s = -1e30f;   // sentinel: ex2(arg) -> 0, so this tap contributes nothing
        }
        sA[i] = make_float4(v[0], v[1], v[2], v[3]);
        sB[i] = make_float4(v[4], v[5], v[6], v[7]);
        sS[i] = s;
    }

    __syncthreads();

    const int tx = threadIdx.x & 63;
    const int tr = threadIdx.x >> 6;   // 0..3

    // Each j-iteration: this thread computes a vertical PAIR of pixels
    // (row0, row0+2). Their 5 tap-rows overlap in 4 -> union is 6 rows,
    // so 30 shared-memory loads serve 50 taps (15 loads/pixel vs 25).
#pragma unroll 1
    for (int j = 0; j < 2; j++) {
        const int rp   = tr + j * 4;                       // 0..7
        const int row0 = ((rp >> 1) << 2) + (rp & 1);      // (0,2),(1,3),(4,6),...,(13,15)
        const int ci0  = (HALO + row0) * RW + HALO + tx;   // center of pixel 0
        const int ci1  = ci0 + 2 * RW;                     // center of pixel 1

        const float4 ca0 = sA[ci0]; const float4 cb0 = sB[ci0]; const float sc0 = sS[ci0];
        const float4 ca1 = sA[ci1]; const float4 cb1 = sB[ci1]; const float sc1 = sS[ci1];

        const float p00 = rc[0]*ca0.x, p01 = rc[1]*ca0.y, p02 = rc[2]*ca0.z, p03 = rc[3]*ca0.w;
        const float p04 = rc[4]*cb0.x, p05 = rc[5]*cb0.y, p06 = rc[6]*cb0.z, p07 = rc[7]*cb0.w;
        const float p10 = rc[0]*ca1.x, p11 = rc[1]*ca1.y, p12 = rc[2]*ca1.z, p13 = rc[3]*ca1.w;
        const float p14 = rc[4]*cb1.x, p15 = rc[5]*cb1.y, p16 = rc[6]*cb1.z, p17 = rc[7]*cb1.w;

        float num0[DYN], num1[DYN];
#pragma unroll
        for (int c = 0; c < DYN; c++) { num0[c] = 0.f; num1[c] = 0.f; }
        float den0 = 0.f, den1 = 0.f;

#pragma unroll
        for (int iy = 0; iy < 6; iy++) {                   // tap row = row0 - 4 + 2*iy
            const int rbase = ci0 + (2 * iy - 4) * RW;
#pragma unroll
            for (int kx = 0; kx < 5; kx++) {
                const int ni = rbase + 2 * kx - 4;
                const float4 na = sA[ni];
                const float4 nb = sB[ni];
                const float  sn = sS[ni];
                const float nv[8] = {na.x, na.y, na.z, na.w, nb.x, nb.y, nb.z, nb.w};

                if (iy <= 4) {   // valid tap for pixel 0 (ky = iy)
                    float dA = fmaf(p03, na.w, fmaf(p02, na.z, fmaf(p01, na.y, p00 * na.x)));
                    float dB = fmaf(p07, nb.w, fmaf(p06, nb.z, fmaf(p05, nb.y, p04 * nb.x)));
                    float arg = fmaf(dA + dB, -2.0f, sn + (sc0 + sLW[iy * 5 + kx]));
                    float w;
                    asm("ex2.approx.ftz.f32 %0, %1;" : "=f"(w) : "f"(arg));
                    den0 += w;
#pragma unroll
                    for (int c = 0; c < DYN; c++) num0[c] = fmaf(w, nv[c], num0[c]);
                }
                if (iy >= 1) {   // valid tap for pixel 1 (ky = iy - 1)
                    float dA = fmaf(p13, na.w, fmaf(p12, na.z, fmaf(p11, na.y, p10 * na.x)));
                    float dB = fmaf(p17, nb.w, fmaf(p16, nb.z, fmaf(p15, nb.y, p14 * nb.x)));
                    float arg = fmaf(dA + dB, -2.0f, sn + (sc1 + sLW[(iy - 1) * 5 + kx]));
                    float w;
                    asm("ex2.approx.ftz.f32 %0, %1;" : "=f"(w) : "f"(arg));
                    den1 += w;
#pragma unroll
                    for (int c = 0; c < DYN; c++) num1[c] = fmaf(w, nv[c], num1[c]);
                }
            }
        }

        float rd0, rd1;
        asm("rcp.approx.ftz.f32 %0, %1;" : "=f"(rd0) : "f"(den0));
        asm("rcp.approx.ftz.f32 %0, %1;" : "=f"(rd1) : "f"(den1));

        // exact grid: 1088 = 68*16, 1920 = 30*64 -> no bounds check needed
        const int gy0 = blockIdx.y * TH + row0;
        const int gx  = blockIdx.x * TW + tx;
        float* op0 = out + (((size_t)b * DYN) * Hc + gy0) * Wc + gx;
        float* op1 = op0 + 2 * Wc;
#pragma unroll
        for (int c = 0; c < DYN; c++) {
            op0[(size_t)c * Hc * Wc] = num0[c] * rd0;
            op1[(size_t)c * Hc * Wc] = num1[c] * rd1;
        }
    }
}

extern "C" void kernel_launch(void* const* d_in, const int* in_sizes, int n_in,
                              void* d_out, int out_size) {
    const float* inp    = (const float*)d_in[0];
    const float* params = (const float*)d_in[1];
    const float* kern   = (const float*)d_in[2];
    float* out = (float*)d_out;
    (void)in_sizes; (void)n_in;

    int dyn = out_size / (Bc * Hc * Wc);   // dynamic_size derived from output element count
    if (dyn < 1) dyn = 1;
    if (dyn > 8) dyn = 8;

    bf_setup<<<1, 32>>>(params, kern);

    dim3 grid(Wc / TW, (Hc + TH - 1) / TH, Bc);

#define BF_LAUNCH(D)                                                                     \
    {                                                                                    \
        cudaFuncSetAttribute(bf_main<D>, cudaFuncAttributeMaxDynamicSharedMemorySize,    \
                             SMEM_BYTES);                                                \
        bf_main<D><<<grid, 256, SMEM_BYTES>>>(inp, out);                                 \
    }

    switch (dyn) {
        case 1: BF_LAUNCH(1); break;
        case 2: BF_LAUNCH(2); break;
        case 3: BF_LAUNCH(3); break;
        case 4: BF_LAUNCH(4); break;
        case 5: BF_LAUNCH(5); break;
        case 6: BF_LAUNCH(6); break;
        case 7: BF_LAUNCH(7); break;
        case 8: BF_LAUNCH(8); break;
        default: BF_LAUNCH(3); break;
    }
#undef BF_LAUNCH
}

// round 10
// speedup vs baseline: 1.7493x; 1.1111x over previous
#include <cuda_runtime.h>

#define L2E 1.4426950408889634f

static constexpr int Bc = 2, Cc = 8, Hc = 1088, Wc = 1920;
static constexpr int TW = 64, TH = 16, HALO = 4;       // dilation=2, radius=2 -> halo 4
static constexpr int RW = TW + 2 * HALO;               // 72
static constexpr int RH = TH + 2 * HALO;               // 24
// A(float4) + B(float4) + S(float) per region pixel, + 32 floats of coeffs
static constexpr int SMEM_BYTES = RH * RW * (16 + 16 + 4) + 32 * 4;

using u64 = unsigned long long;

__device__ __forceinline__ u64 pack2(float lo, float hi) {
    u64 r; asm("mov.b64 %0, {%1, %2};" : "=l"(r) : "f"(lo), "f"(hi)); return r;
}
__device__ __forceinline__ void unpack2(u64 v, float& lo, float& hi) {
    asm("mov.b64 {%0, %1}, %2;" : "=f"(lo), "=f"(hi) : "l"(v));
}
__device__ __forceinline__ u64 fma2(u64 a, u64 b, u64 c) {
    u64 r; asm("fma.rn.f32x2 %0, %1, %2, %3;" : "=l"(r) : "l"(a), "l"(b), "l"(c)); return r;
}
__device__ __forceinline__ u64 mul2(u64 a, u64 b) {
    u64 r; asm("mul.rn.f32x2 %0, %1, %2;" : "=l"(r) : "l"(a), "l"(b)); return r;
}

// Precomputed coefficients (written by setup kernel, read by main kernel)
__device__ float g_rcp[8];   // -p[c]^2 * log2(e)
__device__ float g_lw[25];   // log2(tk[t]) + log2(e)*(sx*dx^2 + sy*dy^2)

__global__ void bf_setup(const float* __restrict__ params,
                         const float* __restrict__ kern) {
    if (threadIdx.x == 0) {
        float p[10];
#pragma unroll
        for (int i = 0; i < 10; i++) p[i] = params[i];
#pragma unroll
        for (int c = 0; c < 8; c++) g_rcp[c] = -p[c] * p[c] * L2E;
        float sx = -p[8] * p[8];
        float sy = -p[9] * p[9];
        // softmax(kernel.flatten() / K), K = 5
        float k[25], m = -1e30f;
        for (int i = 0; i < 25; i++) { k[i] = kern[i] * 0.2f; m = fmaxf(m, k[i]); }
        float s = 0.f;
        for (int i = 0; i < 25; i++) { k[i] = expf(k[i] - m); s += k[i]; }
        float inv = 1.0f / s;
        for (int t = 0; t < 25; t++) {
            int ky = t / 5, kx = t % 5;
            float dy = (float)((ky - 2) * 2);   // dilation = 2
            float dx = (float)((kx - 2) * 2);
            g_lw[t] = log2f(k[t] * inv) + L2E * (sx * dx * dx + sy * dy * dy);
        }
    }
}

template <int DYN>
__global__ __launch_bounds__(256, 2)
void bf_main(const float* __restrict__ inp, float* __restrict__ out) {
    extern __shared__ float smem[];
    float4* sA = (float4*)smem;           // channels 0..3
    float4* sB = sA + RH * RW;            // channels 4..7
    float*  sS = (float*)(sB + RH * RW);  // s = sum_c rc_c * v_c^2  (or -1e30 if OOB)
    float*  sLW = sS + RH * RW;           // 25 tap constants (broadcast reads)

    const int b  = blockIdx.z;
    const int x0 = blockIdx.x * TW - HALO;
    const int y0 = blockIdx.y * TH - HALO;

    // stage tap coefficients into smem (broadcast LDS, conflict-free)
    if (threadIdx.x < 25) sLW[threadIdx.x] = g_lw[threadIdx.x];

    float rc[8];
#pragma unroll
    for (int c = 0; c < 8; c++) rc[c] = g_rcp[c];

    const float* ibase = inp + (size_t)b * Cc * Hc * Wc;

    // ---- cooperative tile load: global (planar) -> smem (pixel-major float4 pairs) ----
    for (int i = threadIdx.x; i < RH * RW; i += 256) {
        int ry = i / RW, rx = i - ry * RW;
        int gy = y0 + ry, gx = x0 + rx;
        float v[8];
        float s;
        if ((unsigned)gy < (unsigned)Hc && (unsigned)gx < (unsigned)Wc) {
            const float* p = ibase + gy * Wc + gx;
#pragma unroll
            for (int c = 0; c < 8; c++) v[c] = p[c * Hc * Wc];
            s = 0.f;
#pragma unroll
            for (int c = 0; c < 8; c++) s = fmaf(rc[c] * v[c], v[c], s);
        } else {
#pragma unroll
            for (int c = 0; c < 8; c++) v[c] = 0.f;
            s = -1e30f;   // sentinel: ex2(arg) -> 0, so this tap contributes nothing
        }
        sA[i] = make_float4(v[0], v[1], v[2], v[3]);
        sB[i] = make_float4(v[4], v[5], v[6], v[7]);
        sS[i] = s;
    }

    __syncthreads();

    const int tx = threadIdx.x & 63;
    const int tr = threadIdx.x >> 6;   // 0..3

    constexpr int NP = (DYN + 1) / 2;  // channel pairs accumulated as f32x2

    const ulonglong2* sA2 = (const ulonglong2*)sA;
    const ulonglong2* sB2 = (const ulonglong2*)sB;

    // Each j-iteration: this thread computes a vertical PAIR of pixels
    // (row0, row0+2). Union of their tap rows is 6 rows -> 30 loads / 50 taps.
#pragma unroll 1
    for (int j = 0; j < 2; j++) {
        const int rp   = tr + j * 4;                       // 0..7
        const int row0 = ((rp >> 1) << 2) + (rp & 1);      // (0,2),(1,3),(4,6),...,(13,15)
        const int ci0  = (HALO + row0) * RW + HALO + tx;   // center of pixel 0
        const int ci1  = ci0 + 2 * RW;                     // center of pixel 1

        const float4 ca0 = sA[ci0]; const float4 cb0 = sB[ci0]; const float sc0 = sS[ci0];
        const float4 ca1 = sA[ci1]; const float4 cb1 = sB[ci1]; const float sc1 = sS[ci1];

        // packed q-pairs: q[p] = (rc[2p]*center[2p], rc[2p+1]*center[2p+1])
        const u64 q0_01 = pack2(rc[0]*ca0.x, rc[1]*ca0.y);
        const u64 q0_23 = pack2(rc[2]*ca0.z, rc[3]*ca0.w);
        const u64 q0_45 = pack2(rc[4]*cb0.x, rc[5]*cb0.y);
        const u64 q0_67 = pack2(rc[6]*cb0.z, rc[7]*cb0.w);
        const u64 q1_01 = pack2(rc[0]*ca1.x, rc[1]*ca1.y);
        const u64 q1_23 = pack2(rc[2]*ca1.z, rc[3]*ca1.w);
        const u64 q1_45 = pack2(rc[4]*cb1.x, rc[5]*cb1.y);
        const u64 q1_67 = pack2(rc[6]*cb1.z, rc[7]*cb1.w);

        u64 num0[NP], num1[NP];
#pragma unroll
        for (int p = 0; p < NP; p++) { num0[p] = 0ull; num1[p] = 0ull; }
        float den0 = 0.f, den1 = 0.f;

#pragma unroll
        for (int iy = 0; iy < 6; iy++) {                   // tap row = row0 - 4 + 2*iy
            const int rbase = ci0 + (2 * iy - 4) * RW;
#pragma unroll
            for (int kx = 0; kx < 5; kx++) {
                const int ni = rbase + 2 * kx - 4;
                const ulonglong2 na2 = sA2[ni];            // (c0,c1),(c2,c3) packed
                const ulonglong2 nb2 = sB2[ni];            // (c4,c5),(c6,c7) packed
                const float      sn  = sS[ni];
                const u64 halves[4] = {na2.x, na2.y, nb2.x, nb2.y};

                if (iy <= 4) {   // valid tap for pixel 0 (ky = iy)
                    u64 acc = mul2(q0_67, nb2.y);
                    acc = fma2(q0_45, nb2.x, acc);
                    acc = fma2(q0_23, na2.y, acc);
                    acc = fma2(q0_01, na2.x, acc);
                    float dlo, dhi; unpack2(acc, dlo, dhi);
                    float arg = fmaf(dlo + dhi, -2.0f, sn + (sc0 + sLW[iy * 5 + kx]));
                    float w;
                    asm("ex2.approx.ftz.f32 %0, %1;" : "=f"(w) : "f"(arg));
                    den0 += w;
                    const u64 w2 = pack2(w, w);
#pragma unroll
                    for (int p = 0; p < NP; p++) num0[p] = fma2(w2, halves[p], num0[p]);
                }
                if (iy >= 1) {   // valid tap for pixel 1 (ky = iy - 1)
                    u64 acc = mul2(q1_67, nb2.y);
                    acc = fma2(q1_45, nb2.x, acc);
                    acc = fma2(q1_23, na2.y, acc);
                    acc = fma2(q1_01, na2.x, acc);
                    float dlo, dhi; unpack2(acc, dlo, dhi);
                    float arg = fmaf(dlo + dhi, -2.0f, sn + (sc1 + sLW[(iy - 1) * 5 + kx]));
                    float w;
                    asm("ex2.approx.ftz.f32 %0, %1;" : "=f"(w) : "f"(arg));
                    den1 += w;
                    const u64 w2 = pack2(w, w);
#pragma unroll
                    for (int p = 0; p < NP; p++) num1[p] = fma2(w2, halves[p], num1[p]);
                }
            }
        }

        float rd0, rd1;
        asm("rcp.approx.ftz.f32 %0, %1;" : "=f"(rd0) : "f"(den0));
        asm("rcp.approx.ftz.f32 %0, %1;" : "=f"(rd1) : "f"(den1));

        float o0[2 * NP], o1[2 * NP];
#pragma unroll
        for (int p = 0; p < NP; p++) {
            unpack2(num0[p], o0[2 * p], o0[2 * p + 1]);
            unpack2(num1[p], o1[2 * p], o1[2 * p + 1]);
        }

        // exact grid: 1088 = 68*16, 1920 = 30*64 -> no bounds check needed
        const int gy0 = blockIdx.y * TH + row0;
        const int gx  = blockIdx.x * TW + tx;
        float* op0 = out + (((size_t)b * DYN) * Hc + gy0) * Wc + gx;
        float* op1 = op0 + 2 * Wc;
#pragma unroll
        for (int c = 0; c < DYN; c++) {
            op0[(size_t)c * Hc * Wc] = o0[c] * rd0;
            op1[(size_t)c * Hc * Wc] = o1[c] * rd1;
        }
    }
}

extern "C" void kernel_launch(void* const* d_in, const int* in_sizes, int n_in,
                              void* d_out, int out_size) {
    const float* inp    = (const float*)d_in[0];
    const float* params = (const float*)d_in[1];
    const float* kern   = (const float*)d_in[2];
    float* out = (float*)d_out;
    (void)in_sizes; (void)n_in;

    int dyn = out_size / (Bc * Hc * Wc);   // dynamic_size derived from output element count
    if (dyn < 1) dyn = 1;
    if (dyn > 8) dyn = 8;

    bf_setup<<<1, 32>>>(params, kern);

    dim3 grid(Wc / TW, (Hc + TH - 1) / TH, Bc);

#define BF_LAUNCH(D)                                                                     \
    {                                                                                    \
        cudaFuncSetAttribute(bf_main<D>, cudaFuncAttributeMaxDynamicSharedMemorySize,    \
                             SMEM_BYTES);                                                \
        bf_main<D><<<grid, 256, SMEM_BYTES>>>(inp, out);                                 \
    }

    switch (dyn) {
        case 1: BF_LAUNCH(1); break;
        case 2: BF_LAUNCH(2); break;
        case 3: BF_LAUNCH(3); break;
        case 4: BF_LAUNCH(4); break;
        case 5: BF_LAUNCH(5); break;
        case 6: BF_LAUNCH(6); break;
        case 7: BF_LAUNCH(7); break;
        case 8: BF_LAUNCH(8); break;
        default: BF_LAUNCH(3); break;
    }
#undef BF_LAUNCH
}

// round 11
// speedup vs baseline: 1.7770x; 1.0159x over previous
#include <cuda_runtime.h>

#define L2E 1.4426950408889634f

static constexpr int Bc = 2, Cc = 8, Hc = 1088, Wc = 1920;
static constexpr int TW = 64, TH = 16, HALO = 4;       // dilation=2, radius=2 -> halo 4
static constexpr int RW = TW + 2 * HALO;               // 72
static constexpr int RH = TH + 2 * HALO;               // 24
static constexpr int SMEM_BYTES = RH * RW * (16 + 16 + 4) + 32 * 4;

using u64 = unsigned long long;

__device__ __forceinline__ u64 pack2(float lo, float hi) {
    u64 r; asm("mov.b64 %0, {%1, %2};" : "=l"(r) : "f"(lo), "f"(hi)); return r;
}
__device__ __forceinline__ void unpack2(u64 v, float& lo, float& hi) {
    asm("mov.b64 {%0, %1}, %2;" : "=f"(lo), "=f"(hi) : "l"(v));
}
__device__ __forceinline__ u64 fma2(u64 a, u64 b, u64 c) {
    u64 r; asm("fma.rn.f32x2 %0, %1, %2, %3;" : "=l"(r) : "l"(a), "l"(b), "l"(c)); return r;
}
__device__ __forceinline__ u64 mul2(u64 a, u64 b) {
    u64 r; asm("mul.rn.f32x2 %0, %1, %2;" : "=l"(r) : "l"(a), "l"(b)); return r;
}
// in-row bank swizzle: flip bit1 by bit3 so gapped lane patterns hit distinct banks
__device__ __forceinline__ int sw(int x) { return x ^ ((x & 8) >> 2); }

__device__ float g_rcp[8];   // -p[c]^2 * log2(e)
__device__ float g_lw[25];   // log2(tk[t]) + log2(e)*(sx*dx^2 + sy*dy^2)

__global__ void bf_setup(const float* __restrict__ params,
                         const float* __restrict__ kern) {
    if (threadIdx.x == 0) {
        float p[10];
#pragma unroll
        for (int i = 0; i < 10; i++) p[i] = params[i];
#pragma unroll
        for (int c = 0; c < 8; c++) g_rcp[c] = -p[c] * p[c] * L2E;
        float sx = -p[8] * p[8];
        float sy = -p[9] * p[9];
        float k[25], m = -1e30f;
        for (int i = 0; i < 25; i++) { k[i] = kern[i] * 0.2f; m = fmaxf(m, k[i]); }
        float s = 0.f;
        for (int i = 0; i < 25; i++) { k[i] = expf(k[i] - m); s += k[i]; }
        float inv = 1.0f / s;
        for (int t = 0; t < 25; t++) {
            int ky = t / 5, kx = t % 5;
            float dy = (float)((ky - 2) * 2);
            float dx = (float)((kx - 2) * 2);
            g_lw[t] = log2f(k[t] * inv) + L2E * (sx * dx * dx + sy * dy * dy);
        }
    }
}

template <int DYN>
__global__ __launch_bounds__(256, 2)
void bf_main(const float* __restrict__ inp, float* __restrict__ out) {
    extern __shared__ float smem[];
    float4* sA = (float4*)smem;           // channels 0..3 (pixel-major, swizzled in-row)
    float4* sB = sA + RH * RW;            // channels 4..7
    float*  sS = (float*)(sB + RH * RW);  // s = sum_c rc_c * v_c^2  (or -1e30 if OOB)
    float*  sLW = sS + RH * RW;           // 25 tap constants

    const int b  = blockIdx.z;
    const int x0 = blockIdx.x * TW - HALO;
    const int y0 = blockIdx.y * TH - HALO;

    if (threadIdx.x < 25) sLW[threadIdx.x] = g_lw[threadIdx.x];

    float rc[8];
#pragma unroll
    for (int c = 0; c < 8; c++) rc[c] = g_rcp[c];

    const float* ibase = inp + (size_t)b * Cc * Hc * Wc;

    // ---- cooperative tile load (swizzled within row) ----
    for (int i = threadIdx.x; i < RH * RW; i += 256) {
        int ry = i / RW, rx = i - ry * RW;
        int gy = y0 + ry, gx = x0 + rx;
        float v[8];
        float s;
        if ((unsigned)gy < (unsigned)Hc && (unsigned)gx < (unsigned)Wc) {
            const float* p = ibase + gy * Wc + gx;
#pragma unroll
            for (int c = 0; c < 8; c++) v[c] = p[c * Hc * Wc];
            s = 0.f;
#pragma unroll
            for (int c = 0; c < 8; c++) s = fmaf(rc[c] * v[c], v[c], s);
        } else {
#pragma unroll
            for (int c = 0; c < 8; c++) v[c] = 0.f;
            s = -1e30f;   // ex2 -> 0: tap contributes nothing
        }
        int si = ry * RW + sw(rx);
        sA[si] = make_float4(v[0], v[1], v[2], v[3]);
        sB[si] = make_float4(v[4], v[5], v[6], v[7]);
        sS[si] = s;
    }

    __syncthreads();

    const ulonglong2* sA2 = (const ulonglong2*)sA;
    const ulonglong2* sB2 = (const ulonglong2*)sB;

    // 2x2 quad per thread: rows (row0, row0+2), cols (c0, c0+2).
    // Tap union: 6 rows x 6 cols = 36 records serving 100 taps.
    const int l    = threadIdx.x & 31;
    const int rp   = threadIdx.x >> 5;                  // 0..7
    const int c0   = ((l >> 1) << 2) + (l & 1);         // (0,2),(1,3),(4,6),... pairs
    const int row0 = ((rp >> 1) << 2) + (rp & 1);

    // swizzled column indices of the 6 tap columns (region col = c0 + 2*ix, HALO folds out)
    int swc[6];
#pragma unroll
    for (int ix = 0; ix < 6; ix++) swc[ix] = sw(c0 + 2 * ix);

    // centers: pixel(py,px) is record (iy=py+2, ix=px+2)
    u64 q[4][4];
    float sc[4];
#pragma unroll
    for (int py = 0; py < 2; py++)
#pragma unroll
    for (int px = 0; px < 2; px++) {
        const int p = py * 2 + px;
        const int idx = (row0 + 2 * (py + 2)) * RW + swc[px + 2];
        const ulonglong2 ca = sA2[idx];
        const ulonglong2 cb = sB2[idx];
        sc[p] = sS[idx];
        float a0,a1,a2,a3,b0,b1,b2,b3;
        unpack2(ca.x,a0,a1); unpack2(ca.y,a2,a3);
        unpack2(cb.x,b0,b1); unpack2(cb.y,b2,b3);
        q[p][0] = pack2(rc[0]*a0, rc[1]*a1);
        q[p][1] = pack2(rc[2]*a2, rc[3]*a3);
        q[p][2] = pack2(rc[4]*b0, rc[5]*b1);
        q[p][3] = pack2(rc[6]*b2, rc[7]*b3);
    }

    float den[4] = {0.f, 0.f, 0.f, 0.f};
    float num[4][DYN];
#pragma unroll
    for (int p = 0; p < 4; p++)
#pragma unroll
        for (int c = 0; c < DYN; c++) num[p][c] = 0.f;

#pragma unroll
    for (int iy = 0; iy < 6; iy++) {
#pragma unroll
        for (int ix = 0; ix < 6; ix++) {
            const int idx = (row0 + 2 * iy) * RW + swc[ix];
            const ulonglong2 na = sA2[idx];
            const ulonglong2 nb = sB2[idx];
            const float sn = sS[idx];
            float nv[8];
            unpack2(na.x, nv[0], nv[1]); unpack2(na.y, nv[2], nv[3]);
            unpack2(nb.x, nv[4], nv[5]); unpack2(nb.y, nv[6], nv[7]);

#pragma unroll
            for (int py = 0; py < 2; py++)
#pragma unroll
            for (int px = 0; px < 2; px++) {
                if (iy >= py && iy <= py + 4 && ix >= px && ix <= px + 4) {
                    const int p = py * 2 + px;
                    u64 acc = mul2(q[p][3], nb.y);
                    acc = fma2(q[p][2], nb.x, acc);
                    acc = fma2(q[p][1], na.y, acc);
                    acc = fma2(q[p][0], na.x, acc);
                    float dlo, dhi; unpack2(acc, dlo, dhi);
                    float arg = fmaf(dlo + dhi, -2.0f,
                                     sn + (sc[p] + sLW[(iy - py) * 5 + (ix - px)]));
                    float w;
                    asm("ex2.approx.ftz.f32 %0, %1;" : "=f"(w) : "f"(arg));
                    den[p] += w;
#pragma unroll
                    for (int c = 0; c < DYN; c++) num[p][c] = fmaf(w, nv[c], num[p][c]);
                }
            }
        }
    }

    // exact tiling: no bounds checks needed
    const int gyb = blockIdx.y * TH + row0;
    const int gxb = blockIdx.x * TW + c0;
#pragma unroll
    for (int py = 0; py < 2; py++)
#pragma unroll
    for (int px = 0; px < 2; px++) {
        const int p = py * 2 + px;
        float rd;
        asm("rcp.approx.ftz.f32 %0, %1;" : "=f"(rd) : "f"(den[p]));
        float* op = out + (((size_t)b * DYN) * Hc + (gyb + 2 * py)) * Wc + (gxb + 2 * px);
#pragma unroll
        for (int c = 0; c < DYN; c++) op[(size_t)c * Hc * Wc] = num[p][c] * rd;
    }
}

extern "C" void kernel_launch(void* const* d_in, const int* in_sizes, int n_in,
                              void* d_out, int out_size) {
    const float* inp    = (const float*)d_in[0];
    const float* params = (const float*)d_in[1];
    const float* kern   = (const float*)d_in[2];
    float* out = (float*)d_out;
    (void)in_sizes; (void)n_in;

    int dyn = out_size / (Bc * Hc * Wc);
    if (dyn < 1) dyn = 1;
    if (dyn > 8) dyn = 8;

    bf_setup<<<1, 32>>>(params, kern);

    dim3 grid(Wc / TW, (Hc + TH - 1) / TH, Bc);

#define BF_LAUNCH(D)                                                                     \
    {                                                                                    \
        cudaFuncSetAttribute(bf_main<D>, cudaFuncAttributeMaxDynamicSharedMemorySize,    \
                             SMEM_BYTES);                                                \
        bf_main<D><<<grid, 256, SMEM_BYTES>>>(inp, out);                                 \
    }

    switch (dyn) {
        case 1: BF_LAUNCH(1); break;
        case 2: BF_LAUNCH(2); break;
        case 3: BF_LAUNCH(3); break;
        case 4: BF_LAUNCH(4); break;
        case 5: BF_LAUNCH(5); break;
        case 6: BF_LAUNCH(6); break;
        case 7: BF_LAUNCH(7); break;
        case 8: BF_LAUNCH(8); break;
        default: BF_LAUNCH(3); break;
    }
#undef BF_LAUNCH
}